// round 15
// baseline (speedup 1.0000x reference)
#include <cuda_runtime.h>
#include <cuda_bf16.h>
#include <cstdint>
#include <math.h>

#define C 256
#define NPOS 32768
#define G 8
#define H 4

// ---- scratch --------------------------------------------------------------
__device__ float g_tokens[2 * C * G];          // [b][c][g]
__device__ float g_K[2 * H * 64 * G];          // [b][h][d][g], pre-scaled by 1/8
__device__ float g_V[2 * H * G * 64];          // [b][h][g][d]
__device__ __nv_bfloat16 g_B1h[2 * 32 * 256];  // [b][hg][c]  Ms~^T hi
__device__ __nv_bfloat16 g_B1l[2 * 32 * 256];  // [b][hg][c]  Ms~^T lo
__device__ __nv_bfloat16 g_B2h[2 * 256 * 32];  // [b][o][hg]  P^T hi
__device__ __nv_bfloat16 g_B2l[2 * 256 * 32];  // [b][o][hg]  P^T lo
__device__ float g_cs[2 * 32];                 // colsum of Ms~
__device__ float g_bias[2 * 32];               // Ms_raw . nq_b

// ---- helpers ----------------------------------------------------------------
__device__ __forceinline__ uint32_t smem_to_u32(const void* p) {
    uint32_t a;
    asm("{ .reg .u64 t; cvta.to.shared.u64 t, %1; cvt.u32.u64 %0, t; }"
        : "=r"(a) : "l"(p));
    return a;
}
__device__ __forceinline__ void cpa16(unsigned s, const void* g) {
    asm volatile("cp.async.cg.shared.global [%0], [%1], 16;" :: "r"(s), "l"(g));
}
__device__ __forceinline__ void cpa_commit() { asm volatile("cp.async.commit_group;"); }
__device__ __forceinline__ void cpa_wait1() { asm volatile("cp.async.wait_group 1;"); }
__device__ __forceinline__ void cpa_wait0() { asm volatile("cp.async.wait_group 0;"); }

__device__ __forceinline__ uint32_t bf16pack(float lo, float hi) {
    uint32_t r;
    asm("cvt.rn.bf16x2.f32 %0, %1, %2;" : "=r"(r) : "f"(hi), "f"(lo));
    return r;
}
__device__ __forceinline__ void mma16816(float* d, const uint32_t* a, const uint32_t* b) {
    asm volatile(
        "mma.sync.aligned.m16n8k16.row.col.f32.bf16.bf16.f32 "
        "{%0,%1,%2,%3}, {%4,%5,%6,%7}, {%8,%9}, {%0,%1,%2,%3};"
        : "+f"(d[0]), "+f"(d[1]), "+f"(d[2]), "+f"(d[3])
        : "r"(a[0]), "r"(a[1]), "r"(a[2]), "r"(a[3]), "r"(b[0]), "r"(b[1]));
}

// ---------------------------------------------------------------------------
// pool 16^3 -> 2^3 + depthwise conv + residual. grid 256, 2 channels/block.
// ---------------------------------------------------------------------------
__global__ void k_tokens(const float* __restrict__ x1,
                         const float* __restrict__ dw_w) {
    int bc0 = blockIdx.x * 2;
    int tid = threadIdx.x;
    int w = tid >> 5, lane = tid & 31;
    int gz = w >> 2, gy = (w >> 1) & 1, gx = w & 1;
    __shared__ float pooled[2][8];
    float s[2] = {0.f, 0.f};
#pragma unroll
    for (int cc = 0; cc < 2; cc++) {
        const float* xp = x1 + (size_t)(bc0 + cc) * 4096;
#pragma unroll
        for (int p = 0; p < 2; p++) {
            int idx = lane + p * 32;
            int lz = idx >> 3, ly = idx & 7;
            const float4* r = reinterpret_cast<const float4*>(
                xp + (gz * 8 + lz) * 256 + (gy * 8 + ly) * 16 + gx * 8);
            float4 a = r[0], b4 = r[1];
            s[cc] += a.x + a.y + a.z + a.w + b4.x + b4.y + b4.z + b4.w;
        }
    }
#pragma unroll
    for (int off = 16; off; off >>= 1) {
        s[0] += __shfl_down_sync(0xffffffffu, s[0], off);
        s[1] += __shfl_down_sync(0xffffffffu, s[1], off);
    }
    if (lane == 0) {
        pooled[0][w] = s[0] * (1.0f / 512.0f);
        pooled[1][w] = s[1] * (1.0f / 512.0f);
    }
    __syncthreads();
    int cz = w >> 2, cy = (w >> 1) & 1, cx = w & 1;
    float val[2] = {0.f, 0.f};
    if (lane < 27) {
        int dz = lane / 9 - 1, dy = (lane / 3) % 3 - 1, dx = lane % 3 - 1;
        int nz = cz + dz, ny = cy + dy, nx = cx + dx;
        if ((unsigned)nz < 2u && (unsigned)ny < 2u && (unsigned)nx < 2u) {
            int pi = nz * 4 + ny * 2 + nx;
            val[0] = dw_w[(bc0 & 255) * 27 + lane] * pooled[0][pi];
            val[1] = dw_w[((bc0 + 1) & 255) * 27 + lane] * pooled[1][pi];
        }
    }
#pragma unroll
    for (int off = 16; off; off >>= 1) {
        val[0] += __shfl_down_sync(0xffffffffu, val[0], off);
        val[1] += __shfl_down_sync(0xffffffffu, val[1], off);
    }
    if (lane == 0) {
        g_tokens[bc0 * 8 + w] = pooled[0][w] + val[0];
        g_tokens[(bc0 + 1) * 8 + w] = pooled[1][w] + val[1];
    }
}

// ---------------------------------------------------------------------------
// LN(tokens), K (prescaled), V.  grid 64 = (b*8+g)*4 + quarter  (r12 proven)
// ---------------------------------------------------------------------------
__global__ void k_kv(const float* __restrict__ k_w, const float* __restrict__ v_w,
                     const float* __restrict__ nkv_w, const float* __restrict__ nkv_b) {
    int bid = blockIdx.x;
    int q = bid & 3;
    int bg = bid >> 2;
    int b = bg >> 3, g = bg & 7;
    int tid = threadIdx.x;
    int w = tid >> 5, lane = tid & 31;
    __shared__ float tok[256], tk[256], red[16];
    __shared__ float uu, rstd;
    float t = g_tokens[(b * 256 + tid) * 8 + g];
    tok[tid] = t;
    float s1 = t, s2 = t * t;
#pragma unroll
    for (int off = 16; off; off >>= 1) {
        s1 += __shfl_down_sync(0xffffffffu, s1, off);
        s2 += __shfl_down_sync(0xffffffffu, s2, off);
    }
    if (lane == 0) { red[w] = s1; red[8 + w] = s2; }
    __syncthreads();
    if (tid == 0) {
        float a = 0.f, qq = 0.f;
        for (int i = 0; i < 8; i++) { a += red[i]; qq += red[8 + i]; }
        float u = a * (1.0f / 256.0f);
        float var = qq * (1.0f / 256.0f) - u * u;
        uu = u; rstd = rsqrtf(var + 1e-6f);
    }
    __syncthreads();
    tk[tid] = (t - uu) * rstd * nkv_w[tid] + nkv_b[tid];
    __syncthreads();
#pragma unroll
    for (int oo = 0; oo < 8; oo++) {
        int o = q * 64 + w * 8 + oo;
        const float* kr = k_w + o * 256;
        const float* vr = v_w + o * 256;
        float pk = 0.f, pv = 0.f;
#pragma unroll
        for (int i = 0; i < 8; i++) {
            int c2 = lane + 32 * i;
            pk += kr[c2] * tk[c2];
            pv += vr[c2] * tok[c2];
        }
#pragma unroll
        for (int off = 16; off; off >>= 1) {
            pk += __shfl_down_sync(0xffffffffu, pk, off);
            pv += __shfl_down_sync(0xffffffffu, pv, off);
        }
        if (lane == 0) {
            int h = o >> 6, d = o & 63;
            g_K[((b * 4 + h) * 64 + d) * 8 + g] = pk * 0.125f;
            g_V[((b * 4 + h) * 8 + g) * 64 + d] = pv;
        }
    }
}

// ---------------------------------------------------------------------------
// fused folds (r12 proven). blocks 0..63: B1 + cs/bias; 64..319: B2.
// ---------------------------------------------------------------------------
__global__ void k_fold(const float* __restrict__ q_w, const float* __restrict__ proj_w,
                       const float* __restrict__ nq_w, const float* __restrict__ nq_b) {
    if (blockIdx.x < 64) {
        int bhg = blockIdx.x;
        int b = bhg >> 5, hg = bhg & 31, h = hg >> 3, g = hg & 7;
        int t = threadIdx.x;
        __shared__ float kd[64];
        __shared__ float r1[8], r2[8];
        if (t < 64) kd[t] = g_K[((b * 4 + h) * 64 + t) * 8 + g];
        __syncthreads();
        float s = 0.f;
        const float* qp = q_w + (h * 64) * 256 + t;
#pragma unroll 8
        for (int d = 0; d < 64; d++) s += qp[d * 256] * kd[d];
        float sp = s * nq_w[t];
        float sb = s * nq_b[t];
        __nv_bfloat16 hb = __float2bfloat16(sp);
        g_B1h[b * 8192 + hg * 256 + t] = hb;
        g_B1l[b * 8192 + hg * 256 + t] = __float2bfloat16(sp - __bfloat162float(hb));
        float a1 = sp, a2 = sb;
#pragma unroll
        for (int off = 16; off; off >>= 1) {
            a1 += __shfl_down_sync(0xffffffffu, a1, off);
            a2 += __shfl_down_sync(0xffffffffu, a2, off);
        }
        int w = t >> 5, lane = t & 31;
        if (lane == 0) { r1[w] = a1; r2[w] = a2; }
        __syncthreads();
        if (t == 0) {
            float c1 = 0.f, c2 = 0.f;
            for (int i = 0; i < 8; i++) { c1 += r1[i]; c2 += r2[i]; }
            g_cs[b * 32 + hg] = c1;
            g_bias[b * 32 + hg] = c2;
        }
    } else {
        int bid = blockIdx.x - 64;
        int q = bid & 3;
        int bhg = bid >> 2;
        int b = bhg >> 5, hg = bhg & 31, h = hg >> 3, g = hg & 7;
        int tid = threadIdx.x;
        int w = tid >> 5, lane = tid & 31;
        __shared__ float vd[64];
        if (tid < 64) vd[tid] = g_V[((b * 4 + h) * 8 + g) * 64 + tid];
        __syncthreads();
#pragma unroll
        for (int oo = 0; oo < 8; oo++) {
            int o = q * 64 + w * 8 + oo;
            const float* pw = proj_w + o * 256 + h * 64;
            float p = pw[lane] * vd[lane] + pw[32 + lane] * vd[32 + lane];
#pragma unroll
            for (int off = 16; off; off >>= 1)
                p += __shfl_down_sync(0xffffffffu, p, off);
            if (lane == 0) {
                __nv_bfloat16 hb = __float2bfloat16(p);
                g_B2h[b * 8192 + o * 32 + hg] = hb;
                g_B2l[b * 8192 + o * 32 + hg] = __float2bfloat16(p - __bfloat162float(hb));
            }
        }
    }
}

// ---------------------------------------------------------------------------
// main kernel v6: 128 positions/block, 256 threads, grid 512, 4 CTA/SM (52 KB).
// Warp w owns m-rows [w*16, w*16+16). 16 chunks x 16 channels, double buffer.
// smem (bytes), time-multiplexed:
//  X 0..16896 (2 x 16ch x 132f)      -> B2H@0 (16384) after mainloop
//  B1H@16896(16896) B1L@33792(16896) -> S@16896 (128x33f = 16896),
//     A2H@33792(8192), A2L@41984(8192) -> stage@16896 (32x132f),
//     B2L@33792 (16384) after A2 frags read
//  CS 50688 | BIAS 50816 | U 50944 | R 51456 | TOT 51968
// ---------------------------------------------------------------------------
#define SB_XS   0
#define SB_B2H  0
#define SB_B1H  16896
#define SB_B1L  33792
#define SB_S    16896
#define SB_A2H  33792
#define SB_A2L  41984
#define SB_STG  16896
#define SB_B2L  33792
#define SB_CS   50688
#define SB_BIAS 50816
#define SB_U    50944
#define SB_R    51456
#define SB_TOT  51968

__global__ void __launch_bounds__(256, 4) k_main(
    const float* __restrict__ x2, float* __restrict__ out) {
    extern __shared__ char smc[];
    uint32_t smb = smem_to_u32(smc);
    int tid = threadIdx.x;
    int lane = tid & 31, w = tid >> 5;
    int g = lane >> 2, tg = lane & 3;
    int b = blockIdx.x >> 8;
    int n0 = (blockIdx.x & 255) * 128;
    const float* xb = x2 + (size_t)b * (C * NPOS) + n0;

    // ---- prologue: B1 (group0), X chunk 0 (group1), cs/bias
    {
        const char* s1 = (const char*)g_B1h + b * 16384;
        const char* s2 = (const char*)g_B1l + b * 16384;
        for (int i = tid; i < 1024; i += 256) {
            int r = i >> 5, c2 = i & 31;
            cpa16(smb + SB_B1H + r * 528 + c2 * 16, s1 + r * 512 + c2 * 16);
            cpa16(smb + SB_B1L + r * 528 + c2 * 16, s2 + r * 512 + c2 * 16);
        }
        cpa_commit();
        for (int i = tid; i < 512; i += 256) {
            int r = i >> 5, c2 = i & 31;
            cpa16(smb + SB_XS + r * 528 + c2 * 16, xb + (size_t)r * NPOS + c2 * 4);
        }
        cpa_commit();
        if (tid < 32) ((float*)(smc + SB_CS))[tid] = g_cs[b * 32 + tid];
        else if (tid < 64) ((float*)(smc + SB_BIAS))[tid - 32] = g_bias[b * 32 + tid - 32];
    }

    const uint32_t* b1h = (const uint32_t*)(smc + SB_B1H);
    const uint32_t* b1l = (const uint32_t*)(smc + SB_B1L);
    float d1[4][4] = {};
    float s1v[2] = {}, s2v[2] = {};
    int m0 = w * 16 + g;
    int k0 = 2 * tg;

    for (int ch = 0; ch < 16; ch++) {
        if (ch < 15) {
            const float* src = xb + (size_t)((ch + 1) * 16) * NPOS;
            unsigned dst = smb + SB_XS + ((unsigned)((ch + 1) & 1)) * 8448u;
            for (int i = tid; i < 512; i += 256) {
                int r = i >> 5, c2 = i & 31;
                cpa16(dst + r * 528 + c2 * 16, src + (size_t)r * NPOS + c2 * 4);
            }
            cpa_commit();
            cpa_wait1();
        } else {
            cpa_wait0();
        }
        __syncthreads();
        const float* Xb = (const float*)(smc + SB_XS + ((ch & 1) ? 8448u : 0u));

        float f[8];
        f[0] = Xb[k0 * 132 + m0];           f[1] = Xb[(k0 + 1) * 132 + m0];
        f[2] = Xb[k0 * 132 + m0 + 8];       f[3] = Xb[(k0 + 1) * 132 + m0 + 8];
        f[4] = Xb[(k0 + 8) * 132 + m0];     f[5] = Xb[(k0 + 9) * 132 + m0];
        f[6] = Xb[(k0 + 8) * 132 + m0 + 8]; f[7] = Xb[(k0 + 9) * 132 + m0 + 8];
        s1v[0] += f[0] + f[1] + f[4] + f[5];
        s1v[1] += f[2] + f[3] + f[6] + f[7];
        s2v[0] += f[0] * f[0] + f[1] * f[1] + f[4] * f[4] + f[5] * f[5];
        s2v[1] += f[2] * f[2] + f[3] * f[3] + f[6] * f[6] + f[7] * f[7];
        uint32_t ah[4], al[4];
#pragma unroll
        for (int qd = 0; qd < 4; qd++) {
            uint32_t hp = bf16pack(f[2 * qd], f[2 * qd + 1]);
            float r0 = f[2 * qd]     - __uint_as_float(hp << 16);
            float r1 = f[2 * qd + 1] - __uint_as_float(hp & 0xffff0000u);
            ah[qd] = hp;
            al[qd] = bf16pack(r0, r1);
        }
        int kidx = ch * 8 + tg;
#pragma unroll
        for (int nb = 0; nb < 4; nb++) {
            int n = nb * 8 + g;
            uint32_t bh[2] = { b1h[n * 132 + kidx], b1h[n * 132 + kidx + 4] };
            uint32_t bl[2] = { b1l[n * 132 + kidx], b1l[n * 132 + kidx + 4] };
            mma16816(d1[nb], ah, bh);
            mma16816(d1[nb], al, bh);
            mma16816(d1[nb], ah, bl);
        }
        __syncthreads();   // all warps done with this buffer before next prefetch
    }

    // ---- B2H into dead X region (async)
    {
        const char* s3 = (const char*)g_B2h + b * 16384;
        for (int i = tid; i < 1024; i += 256) {
            int r = i >> 2, c4 = i & 3;
            int dc = c4 ^ ((r & 6) >> 1);
            cpa16(smb + SB_B2H + r * 64 + dc * 16, s3 + r * 64 + c4 * 16);
        }
        cpa_commit();
    }

    // ---- stats butterfly -> U/R
    {
#pragma unroll
        for (int p = 0; p < 2; p++) {
            s1v[p] += __shfl_xor_sync(0xffffffffu, s1v[p], 1);
            s1v[p] += __shfl_xor_sync(0xffffffffu, s1v[p], 2);
            s2v[p] += __shfl_xor_sync(0xffffffffu, s2v[p], 1);
            s2v[p] += __shfl_xor_sync(0xffffffffu, s2v[p], 2);
        }
        if (tg == 0) {
            float* U = (float*)(smc + SB_U);
            float* R = (float*)(smc + SB_R);
#pragma unroll
            for (int p = 0; p < 2; p++) {
                int pos = w * 16 + p * 8 + g;
                float u = s1v[p] * (1.0f / 256.0f);
                U[pos] = u;
                R[pos] = rsqrtf(s2v[p] * (1.0f / 256.0f) - u * u + 1e-6f);
            }
        }
    }

    // ---- D1 -> S (overlays B1H; mainloop final sync ordered all B1 reads)
    float* S = (float*)(smc + SB_S);
#pragma unroll
    for (int nb = 0; nb < 4; nb++) {
        int n = nb * 8 + 2 * tg;
        S[m0 * 33 + n]           = d1[nb][0];
        S[m0 * 33 + n + 1]       = d1[nb][1];
        S[(m0 + 8) * 33 + n]     = d1[nb][2];
        S[(m0 + 8) * 33 + n + 1] = d1[nb][3];
    }
    __syncthreads();

    // ---- LN correction + softmax + A2 pack, per head (low reg pressure)
    uint32_t* a2h = (uint32_t*)(smc + SB_A2H);
    uint32_t* a2l = (uint32_t*)(smc + SB_A2L);
    if (tid < 128) {
        float u = ((const float*)(smc + SB_U))[tid];
        float rstd = ((const float*)(smc + SB_R))[tid];
        const float* cs = (const float*)(smc + SB_CS);
        const float* bi = (const float*)(smc + SB_BIAS);
        int sw = tid & 15;
#pragma unroll
        for (int h = 0; h < 4; h++) {
            float a[8];
            float m = -1e30f;
#pragma unroll
            for (int g2 = 0; g2 < 8; g2++) {
                int i = h * 8 + g2;
                a[g2] = (S[tid * 33 + i] - u * cs[i]) * rstd + bi[i];
                m = fmaxf(m, a[g2]);
            }
            float ssum = 0.f;
#pragma unroll
            for (int g2 = 0; g2 < 8; g2++) { a[g2] = __expf(a[g2] - m); ssum += a[g2]; }
            float inv = 1.0f / ssum;
#pragma unroll
            for (int j = 0; j < 4; j++) {
                float x0 = a[2 * j] * inv, x1 = a[2 * j + 1] * inv;
                uint32_t hp = bf16pack(x0, x1);
                float r0 = x0 - __uint_as_float(hp << 16);
                float r1 = x1 - __uint_as_float(hp & 0xffff0000u);
                int i = h * 4 + j;
                a2h[tid * 16 + (i ^ sw)] = hp;
                a2l[tid * 16 + (i ^ sw)] = bf16pack(r0, r1);
            }
        }
    }
    __syncthreads();

    // ---- A2 fragments -> regs
    uint32_t A2H[2][4], A2L[2][4];
#pragma unroll
    for (int kc = 0; kc < 2; kc++) {
        int ma = m0, mb = m0 + 8;
        int i0 = kc * 8 + tg, i1 = i0 + 4;
        A2H[kc][0] = a2h[ma * 16 + (i0 ^ (ma & 15))];
        A2H[kc][1] = a2h[mb * 16 + (i0 ^ (mb & 15))];
        A2H[kc][2] = a2h[ma * 16 + (i1 ^ (ma & 15))];
        A2H[kc][3] = a2h[mb * 16 + (i1 ^ (mb & 15))];
        A2L[kc][0] = a2l[ma * 16 + (i0 ^ (ma & 15))];
        A2L[kc][1] = a2l[mb * 16 + (i0 ^ (mb & 15))];
        A2L[kc][2] = a2l[ma * 16 + (i1 ^ (ma & 15))];
        A2L[kc][3] = a2l[mb * 16 + (i1 ^ (mb & 15))];
    }
    __syncthreads();       // A2 reads done -> region free for B2L

    // ---- B2L into dead A2 region (async)
    {
        const char* s4 = (const char*)g_B2l + b * 16384;
        for (int i = tid; i < 1024; i += 256) {
            int r = i >> 2, c4 = i & 3;
            int dc = c4 ^ ((r & 6) >> 1);
            cpa16(smb + SB_B2L + r * 64 + dc * 16, s4 + r * 64 + c4 * 16);
        }
        cpa_commit();
    }
    cpa_wait0();           // B2H + B2L resident
    __syncthreads();

    // ---- GEMM2 + staged coalesced stores (8 rounds of 32 outputs)
    const uint32_t* b2h = (const uint32_t*)(smc + SB_B2H);
    const uint32_t* b2l = (const uint32_t*)(smc + SB_B2L);
    float* stg = (float*)(smc + SB_STG);
    float* ob = out + (size_t)b * (C * NPOS) + n0;
    int sw2 = (g & 6) << 1;
    for (int go = 0; go < 8; go++) {
        if (go) __syncthreads();   // prior round's stage reads complete
        float d2[4][4] = {};
#pragma unroll
        for (int nb = 0; nb < 4; nb++) {
            int n = go * 32 + nb * 8 + g;
#pragma unroll
            for (int kc = 0; kc < 2; kc++) {
                int i0 = (kc * 8 + tg) ^ sw2;
                int i1 = (kc * 8 + tg + 4) ^ sw2;
                uint32_t bh[2] = { b2h[n * 16 + i0], b2h[n * 16 + i1] };
                uint32_t bl[2] = { b2l[n * 16 + i0], b2l[n * 16 + i1] };
                mma16816(d2[nb], A2H[kc], bh);
                mma16816(d2[nb], A2L[kc], bh);
                mma16816(d2[nb], A2H[kc], bl);
            }
        }
#pragma unroll
        for (int nb = 0; nb < 4; nb++) {
            int ol = nb * 8 + 2 * tg;
            stg[ol * 132 + m0]           = d2[nb][0];
            stg[(ol + 1) * 132 + m0]     = d2[nb][1];
            stg[ol * 132 + m0 + 8]       = d2[nb][2];
            stg[(ol + 1) * 132 + m0 + 8] = d2[nb][3];
        }
        __syncthreads();
#pragma unroll
        for (int it = 0; it < 4; it++) {
            int idx = tid + it * 256;
            int row = idx >> 5, c4 = idx & 31;
            float4 v = *reinterpret_cast<const float4*>(stg + row * 132 + c4 * 4);
            *reinterpret_cast<float4*>(ob + (size_t)(go * 32 + row) * NPOS + c4 * 4) = v;
        }
    }
}

// ---------------------------------------------------------------------------
extern "C" void kernel_launch(void* const* d_in, const int* in_sizes, int n_in,
                              void* d_out, int out_size) {
    const float* x2     = (const float*)d_in[0];
    const float* x1_low = (const float*)d_in[1];
    const float* q_w    = (const float*)d_in[2];
    const float* k_w    = (const float*)d_in[3];
    const float* v_w    = (const float*)d_in[4];
    const float* dw_w   = (const float*)d_in[5];
    const float* proj_w = (const float*)d_in[6];
    const float* nq_w   = (const float*)d_in[7];
    const float* nq_b   = (const float*)d_in[8];
    const float* nkv_w  = (const float*)d_in[9];
    const float* nkv_b  = (const float*)d_in[10];
    float* out = (float*)d_out;

    cudaFuncSetAttribute(k_main, cudaFuncAttributeMaxDynamicSharedMemorySize, SB_TOT);

    k_tokens<<<256, 256>>>(x1_low, dw_w);
    k_kv<<<64, 256>>>(k_w, v_w, nkv_w, nkv_b);
    k_fold<<<320, 256>>>(q_w, proj_w, nq_w, nq_b);
    k_main<<<512, 256, SB_TOT>>>(x2, out);
}

// round 16
// speedup vs baseline: 1.0610x; 1.0610x over previous
#include <cuda_runtime.h>
#include <cuda_bf16.h>
#include <cstdint>
#include <math.h>

#define C 256
#define NPOS 32768
#define G 8
#define H 4

// ---- scratch --------------------------------------------------------------
__device__ float g_tokens[2 * C * G];          // [b][c][g]
__device__ float g_K[2 * H * 64 * G];          // [b][h][d][g], pre-scaled by 1/8
__device__ float g_V[2 * H * G * 64];          // [b][h][g][d]
__device__ __nv_bfloat16 g_B1h[2 * 32 * 256];  // [b][hg][c]  Ms~^T hi
__device__ __nv_bfloat16 g_B1l[2 * 32 * 256];  // [b][hg][c]  Ms~^T lo
__device__ __nv_bfloat16 g_B2h[2 * 256 * 32];  // [b][o][hg]  P^T hi
__device__ __nv_bfloat16 g_B2l[2 * 256 * 32];  // [b][o][hg]  P^T lo
__device__ float g_cs[2 * 32];                 // colsum of Ms~
__device__ float g_bias[2 * 32];               // Ms_raw . nq_b

// ---- helpers ----------------------------------------------------------------
__device__ __forceinline__ uint32_t smem_to_u32(const void* p) {
    uint32_t a;
    asm("{ .reg .u64 t; cvta.to.shared.u64 t, %1; cvt.u32.u64 %0, t; }"
        : "=r"(a) : "l"(p));
    return a;
}
__device__ __forceinline__ void cpa16(unsigned s, const void* g) {
    asm volatile("cp.async.cg.shared.global [%0], [%1], 16;" :: "r"(s), "l"(g));
}
__device__ __forceinline__ void cpa_commit() { asm volatile("cp.async.commit_group;"); }
__device__ __forceinline__ void cpa_wait1() { asm volatile("cp.async.wait_group 1;"); }
__device__ __forceinline__ void cpa_wait0() { asm volatile("cp.async.wait_group 0;"); }

__device__ __forceinline__ uint32_t bf16pack(float lo, float hi) {
    uint32_t r;
    asm("cvt.rn.bf16x2.f32 %0, %1, %2;" : "=r"(r) : "f"(hi), "f"(lo));
    return r;
}
__device__ __forceinline__ void mma16816(float* d, const uint32_t* a, const uint32_t* b) {
    asm volatile(
        "mma.sync.aligned.m16n8k16.row.col.f32.bf16.bf16.f32 "
        "{%0,%1,%2,%3}, {%4,%5,%6,%7}, {%8,%9}, {%0,%1,%2,%3};"
        : "+f"(d[0]), "+f"(d[1]), "+f"(d[2]), "+f"(d[3])
        : "r"(a[0]), "r"(a[1]), "r"(a[2]), "r"(a[3]), "r"(b[0]), "r"(b[1]));
}

// ---------------------------------------------------------------------------
// pool 16^3 -> 2^3 + depthwise conv + residual. grid 256, 2 channels/block.
// ---------------------------------------------------------------------------
__global__ void k_tokens(const float* __restrict__ x1,
                         const float* __restrict__ dw_w) {
    int bc0 = blockIdx.x * 2;
    int tid = threadIdx.x;
    int w = tid >> 5, lane = tid & 31;
    int gz = w >> 2, gy = (w >> 1) & 1, gx = w & 1;
    __shared__ float pooled[2][8];
    float s[2] = {0.f, 0.f};
#pragma unroll
    for (int cc = 0; cc < 2; cc++) {
        const float* xp = x1 + (size_t)(bc0 + cc) * 4096;
#pragma unroll
        for (int p = 0; p < 2; p++) {
            int idx = lane + p * 32;
            int lz = idx >> 3, ly = idx & 7;
            const float4* r = reinterpret_cast<const float4*>(
                xp + (gz * 8 + lz) * 256 + (gy * 8 + ly) * 16 + gx * 8);
            float4 a = r[0], b4 = r[1];
            s[cc] += a.x + a.y + a.z + a.w + b4.x + b4.y + b4.z + b4.w;
        }
    }
#pragma unroll
    for (int off = 16; off; off >>= 1) {
        s[0] += __shfl_down_sync(0xffffffffu, s[0], off);
        s[1] += __shfl_down_sync(0xffffffffu, s[1], off);
    }
    if (lane == 0) {
        pooled[0][w] = s[0] * (1.0f / 512.0f);
        pooled[1][w] = s[1] * (1.0f / 512.0f);
    }
    __syncthreads();
    int cz = w >> 2, cy = (w >> 1) & 1, cx = w & 1;
    float val[2] = {0.f, 0.f};
    if (lane < 27) {
        int dz = lane / 9 - 1, dy = (lane / 3) % 3 - 1, dx = lane % 3 - 1;
        int nz = cz + dz, ny = cy + dy, nx = cx + dx;
        if ((unsigned)nz < 2u && (unsigned)ny < 2u && (unsigned)nx < 2u) {
            int pi = nz * 4 + ny * 2 + nx;
            val[0] = dw_w[(bc0 & 255) * 27 + lane] * pooled[0][pi];
            val[1] = dw_w[((bc0 + 1) & 255) * 27 + lane] * pooled[1][pi];
        }
    }
#pragma unroll
    for (int off = 16; off; off >>= 1) {
        val[0] += __shfl_down_sync(0xffffffffu, val[0], off);
        val[1] += __shfl_down_sync(0xffffffffu, val[1], off);
    }
    if (lane == 0) {
        g_tokens[bc0 * 8 + w] = pooled[0][w] + val[0];
        g_tokens[(bc0 + 1) * 8 + w] = pooled[1][w] + val[1];
    }
}

// ---------------------------------------------------------------------------
// LN(tokens), K (prescaled), V.  grid 64 = (b*8+g)*4 + quarter
// ---------------------------------------------------------------------------
__global__ void k_kv(const float* __restrict__ k_w, const float* __restrict__ v_w,
                     const float* __restrict__ nkv_w, const float* __restrict__ nkv_b) {
    int bid = blockIdx.x;
    int q = bid & 3;
    int bg = bid >> 2;
    int b = bg >> 3, g = bg & 7;
    int tid = threadIdx.x;
    int w = tid >> 5, lane = tid & 31;
    __shared__ float tok[256], tk[256], red[16];
    __shared__ float uu, rstd;
    float t = g_tokens[(b * 256 + tid) * 8 + g];
    tok[tid] = t;
    float s1 = t, s2 = t * t;
#pragma unroll
    for (int off = 16; off; off >>= 1) {
        s1 += __shfl_down_sync(0xffffffffu, s1, off);
        s2 += __shfl_down_sync(0xffffffffu, s2, off);
    }
    if (lane == 0) { red[w] = s1; red[8 + w] = s2; }
    __syncthreads();
    if (tid == 0) {
        float a = 0.f, qq = 0.f;
        for (int i = 0; i < 8; i++) { a += red[i]; qq += red[8 + i]; }
        float u = a * (1.0f / 256.0f);
        float var = qq * (1.0f / 256.0f) - u * u;
        uu = u; rstd = rsqrtf(var + 1e-6f);
    }
    __syncthreads();
    tk[tid] = (t - uu) * rstd * nkv_w[tid] + nkv_b[tid];
    __syncthreads();
#pragma unroll
    for (int oo = 0; oo < 8; oo++) {
        int o = q * 64 + w * 8 + oo;
        const float* kr = k_w + o * 256;
        const float* vr = v_w + o * 256;
        float pk = 0.f, pv = 0.f;
#pragma unroll
        for (int i = 0; i < 8; i++) {
            int c2 = lane + 32 * i;
            pk += kr[c2] * tk[c2];
            pv += vr[c2] * tok[c2];
        }
#pragma unroll
        for (int off = 16; off; off >>= 1) {
            pk += __shfl_down_sync(0xffffffffu, pk, off);
            pv += __shfl_down_sync(0xffffffffu, pv, off);
        }
        if (lane == 0) {
            int h = o >> 6, d = o & 63;
            g_K[((b * 4 + h) * 64 + d) * 8 + g] = pk * 0.125f;
            g_V[((b * 4 + h) * 8 + g) * 64 + d] = pv;
        }
    }
}

// ---------------------------------------------------------------------------
// fused folds. blocks 0..63: B1 + cs/bias; 64..319: B2.
// ---------------------------------------------------------------------------
__global__ void k_fold(const float* __restrict__ q_w, const float* __restrict__ proj_w,
                       const float* __restrict__ nq_w, const float* __restrict__ nq_b) {
    if (blockIdx.x < 64) {
        int bhg = blockIdx.x;
        int b = bhg >> 5, hg = bhg & 31, h = hg >> 3, g = hg & 7;
        int t = threadIdx.x;
        __shared__ float kd[64];
        __shared__ float r1[8], r2[8];
        if (t < 64) kd[t] = g_K[((b * 4 + h) * 64 + t) * 8 + g];
        __syncthreads();
        float s = 0.f;
        const float* qp = q_w + (h * 64) * 256 + t;
#pragma unroll 8
        for (int d = 0; d < 64; d++) s += qp[d * 256] * kd[d];
        float sp = s * nq_w[t];
        float sb = s * nq_b[t];
        __nv_bfloat16 hb = __float2bfloat16(sp);
        g_B1h[b * 8192 + hg * 256 + t] = hb;
        g_B1l[b * 8192 + hg * 256 + t] = __float2bfloat16(sp - __bfloat162float(hb));
        float a1 = sp, a2 = sb;
#pragma unroll
        for (int off = 16; off; off >>= 1) {
            a1 += __shfl_down_sync(0xffffffffu, a1, off);
            a2 += __shfl_down_sync(0xffffffffu, a2, off);
        }
        int w = t >> 5, lane = t & 31;
        if (lane == 0) { r1[w] = a1; r2[w] = a2; }
        __syncthreads();
        if (t == 0) {
            float c1 = 0.f, c2 = 0.f;
            for (int i = 0; i < 8; i++) { c1 += r1[i]; c2 += r2[i]; }
            g_cs[b * 32 + hg] = c1;
            g_bias[b * 32 + hg] = c2;
        }
    } else {
        int bid = blockIdx.x - 64;
        int q = bid & 3;
        int bhg = bid >> 2;
        int b = bhg >> 5, hg = bhg & 31, h = hg >> 3, g = hg & 7;
        int tid = threadIdx.x;
        int w = tid >> 5, lane = tid & 31;
        __shared__ float vd[64];
        if (tid < 64) vd[tid] = g_V[((b * 4 + h) * 8 + g) * 64 + tid];
        __syncthreads();
#pragma unroll
        for (int oo = 0; oo < 8; oo++) {
            int o = q * 64 + w * 8 + oo;
            const float* pw = proj_w + o * 256 + h * 64;
            float p = pw[lane] * vd[lane] + pw[32 + lane] * vd[32 + lane];
#pragma unroll
            for (int off = 16; off; off >>= 1)
                p += __shfl_down_sync(0xffffffffu, p, off);
            if (lane == 0) {
                __nv_bfloat16 hb = __float2bfloat16(p);
                g_B2h[b * 8192 + o * 32 + hg] = hb;
                g_B2l[b * 8192 + o * 32 + hg] = __float2bfloat16(p - __bfloat162float(hb));
            }
        }
    }
}

// ---------------------------------------------------------------------------
// main kernel v7 (r12 v3 mainloop + register-resident softmax epilogue):
// 256 positions/block, 256 threads, grid 256. 8 chunks x 32 channels.
// GEMM1 D-fragments double as GEMM2 A-fragments (same lane layout) ->
// LN-correct + softmax via quad shfl + A2 pack all in registers.
// smem (bytes), time-multiplexed:
//  X 0..66560 (2 x 32ch x 260f) -> B2H@0 (256x80) B2L@20480 after mainloop
//  B1 66560..100352 (B1H, B1L 528B rows) -> stage(32x260f) in GEMM2
//  CS 100352 | BIAS 100480 | TOT 100608
// ---------------------------------------------------------------------------
#define SB_XS   0
#define SB_B2H  0
#define SB_B2L  20480
#define SB_R2   66560
#define SB_B1H  66560
#define SB_B1L  83456
#define SB_CS   100352
#define SB_BIAS 100480
#define SB_TOT  100608

__global__ void __launch_bounds__(256, 2) k_main(
    const float* __restrict__ x2, float* __restrict__ out) {
    extern __shared__ char smc[];
    uint32_t smb = smem_to_u32(smc);
    int tid = threadIdx.x;
    int lane = tid & 31, w = tid >> 5;
    int g = lane >> 2, tg = lane & 3;
    int b = blockIdx.x >> 7;
    int n0 = (blockIdx.x & 127) * 256;
    const float* xb = x2 + (size_t)b * (C * NPOS) + n0;

    // ---- prologue: B1 (group 0), X chunk 0 (group 1), cs/bias
    {
        const char* s1 = (const char*)g_B1h + b * 16384;
        const char* s2 = (const char*)g_B1l + b * 16384;
        for (int i = tid; i < 1024; i += 256) {
            int r = i >> 5, c2 = i & 31;
            cpa16(smb + SB_B1H + r * 528 + c2 * 16, s1 + r * 512 + c2 * 16);
            cpa16(smb + SB_B1L + r * 528 + c2 * 16, s2 + r * 512 + c2 * 16);
        }
        cpa_commit();
        for (int i = tid; i < 2048; i += 256) {
            int r = i >> 6, c2 = i & 63;
            cpa16(smb + SB_XS + r * 1040 + c2 * 16, xb + (size_t)r * NPOS + c2 * 4);
        }
        cpa_commit();
        if (tid < 32) ((float*)(smc + SB_CS))[tid] = g_cs[b * 32 + tid];
        else if (tid < 64) ((float*)(smc + SB_BIAS))[tid - 32] = g_bias[b * 32 + tid - 32];
    }

    const uint32_t* b1h = (const uint32_t*)(smc + SB_B1H);
    const uint32_t* b1l = (const uint32_t*)(smc + SB_B1L);
    float d1[2][4][4] = {};
    float s1v[2][2] = {}, s2v[2][2] = {};

    for (int ch = 0; ch < 8; ch++) {
        if (ch < 7) {
            const float* src = xb + (size_t)((ch + 1) * 32) * NPOS;
            unsigned dst = smb + SB_XS + ((unsigned)((ch + 1) & 1)) * 33280u;
            for (int i = tid; i < 2048; i += 256) {
                int r = i >> 6, c2 = i & 63;
                cpa16(dst + r * 1040 + c2 * 16, src + (size_t)r * NPOS + c2 * 4);
            }
            cpa_commit();
            cpa_wait1();
        } else {
            cpa_wait0();
        }
        __syncthreads();
        const float* Xb = (const float*)(smc + SB_XS + ((ch & 1) ? 33280u : 0u));

#pragma unroll
        for (int t = 0; t < 2; t++) {
            int m0 = w * 32 + t * 16 + g;
#pragma unroll
            for (int kb = 0; kb < 2; kb++) {
                int k0 = kb * 16 + 2 * tg;
                float f[8];
                f[0] = Xb[k0 * 260 + m0];           f[1] = Xb[(k0 + 1) * 260 + m0];
                f[2] = Xb[k0 * 260 + m0 + 8];       f[3] = Xb[(k0 + 1) * 260 + m0 + 8];
                f[4] = Xb[(k0 + 8) * 260 + m0];     f[5] = Xb[(k0 + 9) * 260 + m0];
                f[6] = Xb[(k0 + 8) * 260 + m0 + 8]; f[7] = Xb[(k0 + 9) * 260 + m0 + 8];
                s1v[t][0] += f[0] + f[1] + f[4] + f[5];
                s1v[t][1] += f[2] + f[3] + f[6] + f[7];
                s2v[t][0] += f[0] * f[0] + f[1] * f[1] + f[4] * f[4] + f[5] * f[5];
                s2v[t][1] += f[2] * f[2] + f[3] * f[3] + f[6] * f[6] + f[7] * f[7];
                uint32_t ah[4], al[4];
#pragma unroll
                for (int qd = 0; qd < 4; qd++) {
                    uint32_t hp = bf16pack(f[2 * qd], f[2 * qd + 1]);
                    float r0 = f[2 * qd]     - __uint_as_float(hp << 16);
                    float r1 = f[2 * qd + 1] - __uint_as_float(hp & 0xffff0000u);
                    ah[qd] = hp;
                    al[qd] = bf16pack(r0, r1);
                }
                int kidx = ch * 16 + kb * 8 + tg;
#pragma unroll
                for (int nb = 0; nb < 4; nb++) {
                    int n = nb * 8 + g;
                    uint32_t bh[2] = { b1h[n * 132 + kidx], b1h[n * 132 + kidx + 4] };
                    uint32_t bl[2] = { b1l[n * 132 + kidx], b1l[n * 132 + kidx + 4] };
                    mma16816(d1[t][nb], ah, bh);
                    mma16816(d1[t][nb], al, bh);
                    mma16816(d1[t][nb], ah, bl);
                }
            }
        }
        __syncthreads();   // all warps done with this buffer before next prefetch
    }

    // ---- B2 into dead X region (async, overlapped with register epilogue)
    {
        const char* s3 = (const char*)g_B2h + b * 16384;
        const char* s4 = (const char*)g_B2l + b * 16384;
        for (int i = tid; i < 1024; i += 256) {
            int r = i >> 2, c2 = i & 3;
            cpa16(smb + SB_B2H + r * 80 + c2 * 16, s3 + r * 64 + c2 * 16);
            cpa16(smb + SB_B2L + r * 80 + c2 * 16, s4 + r * 64 + c2 * 16);
        }
        cpa_commit();
    }

    // ---- stats butterfly (registers only; quad covers all 256 channels)
    float uv[2][2], rv[2][2];
#pragma unroll
    for (int t = 0; t < 2; t++)
#pragma unroll
        for (int p = 0; p < 2; p++) {
            float a1 = s1v[t][p], a2 = s2v[t][p];
            a1 += __shfl_xor_sync(0xffffffffu, a1, 1);
            a1 += __shfl_xor_sync(0xffffffffu, a1, 2);
            a2 += __shfl_xor_sync(0xffffffffu, a2, 1);
            a2 += __shfl_xor_sync(0xffffffffu, a2, 2);
            float u = a1 * (1.0f / 256.0f);
            uv[t][p] = u;
            rv[t][p] = rsqrtf(a2 * (1.0f / 256.0f) - u * u + 1e-6f);
        }

    // ---- LN correction + quad-shfl softmax + A2 pack, all in registers
    uint32_t A2H[2][2][4], A2L[2][2][4];
    {
        const float* cs = (const float*)(smc + SB_CS);
        const float* bi = (const float*)(smc + SB_BIAS);
#pragma unroll
        for (int t = 0; t < 2; t++) {
#pragma unroll
            for (int nb = 0; nb < 4; nb++) {
                int n = nb * 8 + 2 * tg;
                float c0 = cs[n], c1 = cs[n + 1];
                float b0 = bi[n], b1 = bi[n + 1];
                d1[t][nb][0] = (d1[t][nb][0] - uv[t][0] * c0) * rv[t][0] + b0;
                d1[t][nb][1] = (d1[t][nb][1] - uv[t][0] * c1) * rv[t][0] + b1;
                d1[t][nb][2] = (d1[t][nb][2] - uv[t][1] * c0) * rv[t][1] + b0;
                d1[t][nb][3] = (d1[t][nb][3] - uv[t][1] * c1) * rv[t][1] + b1;
                // softmax over this head's 8 keys (quad holds them)
#pragma unroll
                for (int p = 0; p < 2; p++) {
                    float v0 = d1[t][nb][2 * p], v1 = d1[t][nb][2 * p + 1];
                    float m = fmaxf(v0, v1);
                    m = fmaxf(m, __shfl_xor_sync(0xffffffffu, m, 1));
                    m = fmaxf(m, __shfl_xor_sync(0xffffffffu, m, 2));
                    float e0 = __expf(v0 - m), e1 = __expf(v1 - m);
                    float ss = e0 + e1;
                    ss += __shfl_xor_sync(0xffffffffu, ss, 1);
                    ss += __shfl_xor_sync(0xffffffffu, ss, 2);
                    float inv = 1.0f / ss;
                    d1[t][nb][2 * p]     = e0 * inv;
                    d1[t][nb][2 * p + 1] = e1 * inv;
                }
            }
            // pack: D1 fragment layout == A2 fragment layout (kc = head pair)
#pragma unroll
            for (int kc = 0; kc < 2; kc++) {
#pragma unroll
                for (int hh = 0; hh < 2; hh++) {
                    const float* dd = d1[t][kc * 2 + hh];
#pragma unroll
                    for (int rr = 0; rr < 2; rr++) {
                        float x0 = dd[2 * rr], x1 = dd[2 * rr + 1];
                        uint32_t hp = bf16pack(x0, x1);
                        float r0 = x0 - __uint_as_float(hp << 16);
                        float r1 = x1 - __uint_as_float(hp & 0xffff0000u);
                        A2H[t][kc][hh * 2 + rr] = hp;
                        A2L[t][kc][hh * 2 + rr] = bf16pack(r0, r1);
                    }
                }
            }
        }
    }
    cpa_wait0();           // B2 resident
    __syncthreads();       // B2 visible to all; B1/stage region free

    // ---- GEMM2 + staged coalesced stores (8 rounds of 32 outputs)
    const uint32_t* b2h = (const uint32_t*)(smc + SB_B2H);
    const uint32_t* b2l = (const uint32_t*)(smc + SB_B2L);
    float* stg = (float*)(smc + SB_R2);
    float* ob = out + (size_t)b * (C * NPOS) + n0;
    for (int go = 0; go < 8; go++) {
        float d2[2][4][4] = {};
#pragma unroll
        for (int t = 0; t < 2; t++)
#pragma unroll
            for (int nb = 0; nb < 4; nb++) {
                int n = go * 32 + nb * 8 + g;
#pragma unroll
                for (int kc = 0; kc < 2; kc++) {
                    uint32_t bh[2] = { b2h[n * 20 + kc * 8 + tg], b2h[n * 20 + kc * 8 + tg + 4] };
                    uint32_t bl[2] = { b2l[n * 20 + kc * 8 + tg], b2l[n * 20 + kc * 8 + tg + 4] };
                    mma16816(d2[t][nb], A2H[t][kc], bh);
                    mma16816(d2[t][nb], A2L[t][kc], bh);
                    mma16816(d2[t][nb], A2H[t][kc], bl);
                }
            }
        if (go) __syncthreads();   // prior round's stage reads complete
#pragma unroll
        for (int t = 0; t < 2; t++)
#pragma unroll
            for (int nb = 0; nb < 4; nb++) {
                int ol = nb * 8 + 2 * tg;
                int m = w * 32 + t * 16 + g;
                stg[ol * 260 + m]           = d2[t][nb][0];
                stg[(ol + 1) * 260 + m]     = d2[t][nb][1];
                stg[ol * 260 + m + 8]       = d2[t][nb][2];
                stg[(ol + 1) * 260 + m + 8] = d2[t][nb][3];
            }
        __syncthreads();
#pragma unroll
        for (int it = 0; it < 8; it++) {
            int idx = tid + it * 256;
            int row = idx >> 6, c4 = idx & 63;
            float4 v = *reinterpret_cast<const float4*>(stg + row * 260 + c4 * 4);
            *reinterpret_cast<float4*>(ob + (size_t)(go * 32 + row) * NPOS + c4 * 4) = v;
        }
    }
}

// ---------------------------------------------------------------------------
extern "C" void kernel_launch(void* const* d_in, const int* in_sizes, int n_in,
                              void* d_out, int out_size) {
    const float* x2     = (const float*)d_in[0];
    const float* x1_low = (const float*)d_in[1];
    const float* q_w    = (const float*)d_in[2];
    const float* k_w    = (const float*)d_in[3];
    const float* v_w    = (const float*)d_in[4];
    const float* dw_w   = (const float*)d_in[5];
    const float* proj_w = (const float*)d_in[6];
    const float* nq_w   = (const float*)d_in[7];
    const float* nq_b   = (const float*)d_in[8];
    const float* nkv_w  = (const float*)d_in[9];
    const float* nkv_b  = (const float*)d_in[10];
    float* out = (float*)d_out;

    cudaFuncSetAttribute(k_main, cudaFuncAttributeMaxDynamicSharedMemorySize, SB_TOT);

    k_tokens<<<256, 256>>>(x1_low, dw_w);
    k_kv<<<64, 256>>>(k_w, v_w, nkv_w, nkv_b);
    k_fold<<<320, 256>>>(q_w, proj_w, nq_w, nq_b);
    k_main<<<256, 256, SB_TOT>>>(x2, out);
}